// round 2
// baseline (speedup 1.0000x reference)
#include <cuda_runtime.h>
#include <cstdint>

#define BB   16
#define HH   64
#define WW   64
#define CC   512
#define RR   256
#define NSEL 64
#define PHW  7
#define POOLED_ELEMS (BB * NSEL * PHW * PHW * CC)  // 25,690,112

__device__ int4 g_roiclip[BB * NSEL];

__device__ __forceinline__ void fix_axis(int& mn, int& mx, int ps, int fs) {
    int pad = ps - (mx - mn);
    if (pad > 0) {
        if (mn < (pad >> 1))                { mn = 0;       mx = ps; }
        else if (fs - mx < ((1 + pad) >> 1)){ mn = fs - ps; mx = fs; }
        else { mn -= (pad >> 1); mx += (1 + pad) >> 1; }
    }
}

__global__ __launch_bounds__(RR)
void nms_clip_kernel(const float* __restrict__ roi, float* __restrict__ out, int write_tail) {
    __shared__ float4 sbox[RR];                 // x1, y1, x2, y2
    __shared__ float  sarea[RR];
    __shared__ unsigned long long smask[RR][4]; // lower-triangle suppression bitmask
    __shared__ int sidx[NSEL];

    const int b = blockIdx.x;
    const int t = threadIdx.x;

    const float4 rv = ((const float4*)roi)[b * RR + t];
    const float x1 = rv.x, y1 = rv.y;
    const float x2 = rv.x + rv.z, y2 = rv.y + rv.w;
    const float area = (y2 - y1) * (x2 - x1);
    sbox[t]  = make_float4(x1, y1, x2, y2);
    sarea[t] = area;
    __syncthreads();

    // Build suppression row (only j < t is ever consulted by the resolver).
#pragma unroll
    for (int g = 0; g < 4; ++g) {
        unsigned long long mg = 0ull;
        const int jend = min(t, (g + 1) * 64);
        for (int j = g * 64; j < jend; ++j) {
            const float4 o = sbox[j];
            const float ih = fmaxf(fminf(y2, o.w) - fmaxf(y1, o.y), 0.0f);
            const float iw = fmaxf(fminf(x2, o.z) - fmaxf(x1, o.x), 0.0f);
            const float inter = ih * iw;
            const float uni   = area + sarea[j] - inter;
            // exact IEEE divide so the >0.4 decision matches JAX bit-for-bit
            const float iou = (uni > 0.0f) ? __fdiv_rn(inter, uni) : 0.0f;
            if (iou > 0.4f) mg |= 1ull << (j & 63);
        }
        smask[t][g] = mg;
    }
    __syncthreads();

    // Sequential greedy resolve on one thread (registers only, static indexing).
    if (t == 0) {
        unsigned long long keep0 = 0, keep1 = 0, keep2 = 0;
        int n = 0;
#pragma unroll
        for (int g = 0; g < 4; ++g) {
            unsigned long long kg = 0ull;
            for (int k = 0; k < 64 && n < NSEL; ++k) {
                const int i = (g << 6) | k;
                unsigned long long s = kg & smask[i][g];
                if (g > 0) s |= keep0 & smask[i][0];
                if (g > 1) s |= keep1 & smask[i][1];
                if (g > 2) s |= keep2 & smask[i][2];
                if (s == 0ull) { kg |= 1ull << k; sidx[n++] = i; }
            }
            if (g == 0) keep0 = kg;
            else if (g == 1) keep1 = kg;
            else if (g == 2) keep2 = kg;
        }
        for (int q = n; q < NSEL; ++q) sidx[q] = RR - NSEL + q;  // fill = 192 + q
    }
    __syncthreads();

    // Clip the 64 selected ROIs, publish for the pooling kernel, emit tail output.
    if (t < NSEL) {
        const float4 rr = ((const float4*)roi)[b * RR + sidx[t]];
        int xmin = (int)fmaxf(0.0f, rr.x);
        int ymin = (int)fmaxf(0.0f, rr.y);
        int xmax = (int)fminf((float)WW, rr.x + rr.z);
        int ymax = (int)fminf((float)HH, rr.y + rr.w);
        fix_axis(xmin, xmax, PHW, WW);
        fix_axis(ymin, ymax, PHW, HH);
        int4 rc;
        rc.x = xmin; rc.y = ymin; rc.z = xmax - xmin; rc.w = ymax - ymin;
        g_roiclip[b * NSEL + t] = rc;
        if (write_tail) {
            float* tp = out + (size_t)POOLED_ELEMS + (size_t)(b * NSEL + t) * 4;
            tp[0] = (float)rc.x; tp[1] = (float)rc.y;
            tp[2] = (float)rc.z; tp[3] = (float)rc.w;
        }
    }
}

__device__ __forceinline__ float4 f4max(float4 a, float4 b) {
    return make_float4(fmaxf(a.x, b.x), fmaxf(a.y, b.y),
                       fmaxf(a.z, b.z), fmaxf(a.w, b.w));
}

__global__ __launch_bounds__(128)
void pool_kernel(const float* __restrict__ feat, float* __restrict__ out) {
    const int br = blockIdx.x;
    const int b  = br >> 6;
    const int4 rc = g_roiclip[br];
    const int x = rc.x, y = rc.y, w = rc.z, h = rc.w;
    const int t = threadIdx.x;                       // 0..127, 4 channels each
    const int CV = CC / 4;                           // 128 float4 per position

    const float4* __restrict__ fm = (const float4*)feat + (size_t)b * HH * WW * CV;
    float4* __restrict__ o = (float4*)out + (size_t)br * (PHW * PHW) * CV;

    const float4 NEG4 = make_float4(-__int_as_float(0x7f800000),
                                    -__int_as_float(0x7f800000),
                                    -__int_as_float(0x7f800000),
                                    -__int_as_float(0x7f800000));

    // 6x6 direct copy: out[i][j] = fm[y+i][x+j]
#pragma unroll
    for (int i = 0; i < 6; ++i) {
#pragma unroll
        for (int j = 0; j < 6; ++j) {
            o[(i * 7 + j) * CV + t] = fm[((y + i) * WW + (x + j)) * CV + t];
        }
    }

    // last column: out[i][6] = max over jj in [x+6, x+w)
#pragma unroll
    for (int i = 0; i < 6; ++i) {
        float4 a0 = NEG4, a1 = NEG4;
        const float4* row = fm + (size_t)(y + i) * WW * CV;
        int jj = x + 6;
        for (; jj + 1 < x + w; jj += 2) {
            a0 = f4max(a0, row[jj * CV + t]);
            a1 = f4max(a1, row[(jj + 1) * CV + t]);
        }
        if (jj < x + w) a0 = f4max(a0, row[jj * CV + t]);
        o[(i * 7 + 6) * CV + t] = f4max(a0, a1);
    }

    // last row: out[6][j] = max over ii in [y+6, y+h)
#pragma unroll
    for (int j = 0; j < 6; ++j) {
        float4 a0 = NEG4, a1 = NEG4;
        int ii = y + 6;
        for (; ii + 1 < y + h; ii += 2) {
            a0 = f4max(a0, fm[(ii * WW + x + j) * CV + t]);
            a1 = f4max(a1, fm[((ii + 1) * WW + x + j) * CV + t]);
        }
        if (ii < y + h) a0 = f4max(a0, fm[(ii * WW + x + j) * CV + t]);
        o[(42 + j) * CV + t] = f4max(a0, a1);
    }

    // corner: max over [y+6, y+h) x [x+6, x+w)
    {
        float4 a0 = NEG4, a1 = NEG4;
        for (int ii = y + 6; ii < y + h; ++ii) {
            const float4* row = fm + (size_t)ii * WW * CV;
            int jj = x + 6;
            for (; jj + 1 < x + w; jj += 2) {
                a0 = f4max(a0, row[jj * CV + t]);
                a1 = f4max(a1, row[(jj + 1) * CV + t]);
            }
            if (jj < x + w) a0 = f4max(a0, row[jj * CV + t]);
        }
        o[48 * CV + t] = f4max(a0, a1);
    }
}

extern "C" void kernel_launch(void* const* d_in, const int* in_sizes, int n_in,
                              void* d_out, int out_size) {
    const float* feat = (const float*)d_in[0];
    const float* roi  = (const float*)d_in[1];
    // defensive: identify inputs by size (features = 33,554,432; roi = 16,384)
    if (n_in >= 2 && in_sizes[0] == BB * RR * 4) {
        feat = (const float*)d_in[1];
        roi  = (const float*)d_in[0];
    }
    float* out = (float*)d_out;
    const int write_tail = (out_size >= POOLED_ELEMS + BB * NSEL * 4) ? 1 : 0;

    nms_clip_kernel<<<BB, RR>>>(roi, out, write_tail);
    pool_kernel<<<BB * NSEL, 128>>>(feat, out);
}

// round 3
// speedup vs baseline: 1.2788x; 1.2788x over previous
#include <cuda_runtime.h>
#include <cstdint>

#define BB   16
#define HH   64
#define WW   64
#define CC   512
#define RR   256
#define NSEL 64
#define PHW  7
#define POOLED_ELEMS (BB * NSEL * PHW * PHW * CC)  // 25,690,112

__device__ int4 g_roiclip[BB * NSEL];
__device__ int  g_order[BB * NSEL];   // rank-major (big-first) schedule: [rank*BB + b] -> slot

__device__ __forceinline__ void fix_axis(int& mn, int& mx, int ps, int fs) {
    int pad = ps - (mx - mn);
    if (pad > 0) {
        if (mn < (pad >> 1))                { mn = 0;       mx = ps; }
        else if (fs - mx < ((1 + pad) >> 1)){ mn = fs - ps; mx = fs; }
        else { mn -= (pad >> 1); mx += (1 + pad) >> 1; }
    }
}

__global__ __launch_bounds__(RR)
void nms_clip_kernel(const float* __restrict__ roi, float* __restrict__ out, int write_tail) {
    __shared__ float4 sbox[RR];                 // x1, y1, x2, y2
    __shared__ float  sarea[RR];
    __shared__ unsigned long long smask[RR][4]; // lower-triangle suppression bitmask
    __shared__ int sidx[NSEL];
    __shared__ int sarea_i[NSEL];

    const int b = blockIdx.x;
    const int t = threadIdx.x;

    const float4 rv = ((const float4*)roi)[b * RR + t];
    const float x1 = rv.x, y1 = rv.y;
    const float x2 = rv.x + rv.z, y2 = rv.y + rv.w;
    const float area = (y2 - y1) * (x2 - x1);
    sbox[t]  = make_float4(x1, y1, x2, y2);
    sarea[t] = area;
    __syncthreads();

    // Build suppression row (only j < t is ever consulted by the resolver).
#pragma unroll
    for (int g = 0; g < 4; ++g) {
        unsigned long long mg = 0ull;
        const int jend = min(t, (g + 1) * 64);
        for (int j = g * 64; j < jend; ++j) {
            const float4 o = sbox[j];
            const float ih = fmaxf(fminf(y2, o.w) - fmaxf(y1, o.y), 0.0f);
            const float iw = fmaxf(fminf(x2, o.z) - fmaxf(x1, o.x), 0.0f);
            const float inter = ih * iw;
            const float uni   = area + sarea[j] - inter;
            // exact IEEE divide so the >0.4 decision matches JAX bit-for-bit
            const float iou = (uni > 0.0f) ? __fdiv_rn(inter, uni) : 0.0f;
            if (iou > 0.4f) mg |= 1ull << (j & 63);
        }
        smask[t][g] = mg;
    }
    __syncthreads();

    // Sequential greedy resolve on one thread (registers only, static indexing).
    if (t == 0) {
        unsigned long long keep0 = 0, keep1 = 0, keep2 = 0;
        int n = 0;
#pragma unroll
        for (int g = 0; g < 4; ++g) {
            unsigned long long kg = 0ull;
            for (int k = 0; k < 64 && n < NSEL; ++k) {
                const int i = (g << 6) | k;
                unsigned long long s = kg & smask[i][g];
                if (g > 0) s |= keep0 & smask[i][0];
                if (g > 1) s |= keep1 & smask[i][1];
                if (g > 2) s |= keep2 & smask[i][2];
                if (s == 0ull) { kg |= 1ull << k; sidx[n++] = i; }
            }
            if (g == 0) keep0 = kg;
            else if (g == 1) keep1 = kg;
            else if (g == 2) keep2 = kg;
        }
        for (int q = n; q < NSEL; ++q) sidx[q] = RR - NSEL + q;  // fill = 192 + q
    }
    __syncthreads();

    // Clip the 64 selected ROIs, publish for the pooling kernel, emit tail output.
    if (t < NSEL) {
        const float4 rr = ((const float4*)roi)[b * RR + sidx[t]];
        int xmin = (int)fmaxf(0.0f, rr.x);
        int ymin = (int)fmaxf(0.0f, rr.y);
        int xmax = (int)fminf((float)WW, rr.x + rr.z);
        int ymax = (int)fminf((float)HH, rr.y + rr.w);
        fix_axis(xmin, xmax, PHW, WW);
        fix_axis(ymin, ymax, PHW, HH);
        int4 rc;
        rc.x = xmin; rc.y = ymin; rc.z = xmax - xmin; rc.w = ymax - ymin;
        g_roiclip[b * NSEL + t] = rc;
        sarea_i[t] = rc.z * rc.w;
        if (write_tail) {
            float* tp = out + (size_t)POOLED_ELEMS + (size_t)(b * NSEL + t) * 4;
            tp[0] = (float)rc.x; tp[1] = (float)rc.y;
            tp[2] = (float)rc.z; tp[3] = (float)rc.w;
        }
    }
    __syncthreads();

    // Rank ROIs by area descending (big-first schedule for the pool kernel).
    if (t < NSEL) {
        const int a = sarea_i[t];
        int rank = 0;
#pragma unroll 8
        for (int j = 0; j < NSEL; ++j) {
            const int aj = sarea_i[j];
            rank += (aj > a) || (aj == a && j < t);
        }
        g_order[rank * BB + b] = b * NSEL + t;   // rank-major: big ROIs of all batches first
    }
}

__device__ __forceinline__ float4 f4max(float4 a, float4 b) {
    return make_float4(fmaxf(a.x, b.x), fmaxf(a.y, b.y),
                       fmaxf(a.z, b.z), fmaxf(a.w, b.w));
}

__global__ __launch_bounds__(256)
void pool_kernel(const float* __restrict__ feat, float* __restrict__ out) {
    const int slot = g_order[blockIdx.x];
    const int b  = slot >> 6;
    const int4 rc = g_roiclip[slot];
    const int x = rc.x, y = rc.y, w = rc.z, h = rc.w;
    const int t = threadIdx.x & 127;     // channel lane (4 channels each, float4)
    const int g = threadIdx.x >> 7;      // group 0/1
    const int CV = CC / 4;               // 128 float4 per position

    const float4* __restrict__ fm = (const float4*)feat + (size_t)b * HH * WW * CV;
    float4* __restrict__ o = (float4*)out + (size_t)slot * (PHW * PHW) * CV;

    const float NEGF = -__int_as_float(0x7f800000);
    const float4 NEG4 = make_float4(NEGF, NEGF, NEGF, NEGF);

    // ---- 6x6 direct copy: 36 positions, 18 per group ----
#pragma unroll
    for (int k = 0; k < 18; ++k) {
        const int p = g * 18 + k;
        const int i = p / 6, j = p - 6 * i;
        o[(i * 7 + j) * CV + t] = fm[((y + i) * WW + (x + j)) * CV + t];
    }

    // ---- last column: out[i][6] = max over jj in [x+6, x+w); rows 3g..3g+2 ----
#pragma unroll
    for (int k = 0; k < 3; ++k) {
        const int i = 3 * g + k;
        float4 a0 = NEG4, a1 = NEG4, a2 = NEG4, a3 = NEG4;
        const float4* row = fm + (size_t)(y + i) * WW * CV;
        int jj = x + 6;
        for (; jj + 3 < x + w; jj += 4) {
            a0 = f4max(a0, row[(jj    ) * CV + t]);
            a1 = f4max(a1, row[(jj + 1) * CV + t]);
            a2 = f4max(a2, row[(jj + 2) * CV + t]);
            a3 = f4max(a3, row[(jj + 3) * CV + t]);
        }
        for (; jj < x + w; ++jj) a0 = f4max(a0, row[jj * CV + t]);
        o[(i * 7 + 6) * CV + t] = f4max(f4max(a0, a1), f4max(a2, a3));
    }

    // ---- last row: out[6][j] = max over ii in [y+6, y+h); cols 3g..3g+2 ----
#pragma unroll
    for (int k = 0; k < 3; ++k) {
        const int j = 3 * g + k;
        float4 a0 = NEG4, a1 = NEG4, a2 = NEG4, a3 = NEG4;
        const float4* col = fm + (size_t)(x + j) * CV;
        int ii = y + 6;
        for (; ii + 3 < y + h; ii += 4) {
            a0 = f4max(a0, col[(ii    ) * WW * CV + t]);
            a1 = f4max(a1, col[(ii + 1) * WW * CV + t]);
            a2 = f4max(a2, col[(ii + 2) * WW * CV + t]);
            a3 = f4max(a3, col[(ii + 3) * WW * CV + t]);
        }
        for (; ii < y + h; ++ii) a0 = f4max(a0, col[ii * WW * CV + t]);
        o[(42 + j) * CV + t] = f4max(f4max(a0, a1), f4max(a2, a3));
    }

    // ---- corner: max over [y+6, y+h) x [x+6, x+w); rows interleaved between groups ----
    {
        __shared__ float4 sbuf[128];
        float4 a0 = NEG4, a1 = NEG4, a2 = NEG4, a3 = NEG4;
        for (int ii = y + 6 + g; ii < y + h; ii += 2) {
            const float4* row = fm + (size_t)ii * WW * CV;
            int jj = x + 6;
            for (; jj + 3 < x + w; jj += 4) {
                a0 = f4max(a0, row[(jj    ) * CV + t]);
                a1 = f4max(a1, row[(jj + 1) * CV + t]);
                a2 = f4max(a2, row[(jj + 2) * CV + t]);
                a3 = f4max(a3, row[(jj + 3) * CV + t]);
            }
            for (; jj < x + w; ++jj) a0 = f4max(a0, row[jj * CV + t]);
        }
        a0 = f4max(f4max(a0, a1), f4max(a2, a3));
        if (g == 1) sbuf[t] = a0;
        __syncthreads();
        if (g == 0) o[48 * CV + t] = f4max(a0, sbuf[t]);
    }
}

extern "C" void kernel_launch(void* const* d_in, const int* in_sizes, int n_in,
                              void* d_out, int out_size) {
    const float* feat = (const float*)d_in[0];
    const float* roi  = (const float*)d_in[1];
    // defensive: identify inputs by size (features = 33,554,432; roi = 16,384)
    if (n_in >= 2 && in_sizes[0] == BB * RR * 4) {
        feat = (const float*)d_in[1];
        roi  = (const float*)d_in[0];
    }
    float* out = (float*)d_out;
    const int write_tail = (out_size >= POOLED_ELEMS + BB * NSEL * 4) ? 1 : 0;

    nms_clip_kernel<<<BB, RR>>>(roi, out, write_tail);
    pool_kernel<<<BB * NSEL, 256>>>(feat, out);
}

// round 5
// speedup vs baseline: 2.2838x; 1.7859x over previous
#include <cuda_runtime.h>
#include <cstdint>

#define BB   16
#define HH   64
#define WW   64
#define CC   512
#define RR   256
#define NSEL 64
#define PHW  7
#define POOLED_ELEMS (BB * NSEL * PHW * PHW * CC)  // 25,690,112

__device__ int4 g_roiclip[BB * NSEL];
__device__ int  g_order[BB * NSEL];                    // rank-major (big-first) schedule
__device__ unsigned long long g_mask[BB * RR * 4];     // upper-triangle suppression masks

__device__ __forceinline__ void fix_axis(int& mn, int& mx, int ps, int fs) {
    int pad = ps - (mx - mn);
    if (pad > 0) {
        if (mn < (pad >> 1))                { mn = 0;       mx = ps; }
        else if (fs - mx < ((1 + pad) >> 1)){ mn = fs - ps; mx = fs; }
        else { mn -= (pad >> 1); mx += (1 + pad) >> 1; }
    }
}

// ---- Stage 1: suppression masks, upper triangle (j > t), 64 CTAs ----
__global__ __launch_bounds__(RR)
void nms_mask_kernel(const float* __restrict__ roi) {
    __shared__ float4 sbox[RR];   // x1, y1, x2, y2
    __shared__ float  sarea[RR];

    const int b = blockIdx.x;
    const int q = blockIdx.y;     // 64-wide j chunk
    const int t = threadIdx.x;

    const float4 rv = ((const float4*)roi)[b * RR + t];
    const float x1 = rv.x, y1 = rv.y;
    const float x2 = rv.x + rv.z, y2 = rv.y + rv.w;
    const float area = (y2 - y1) * (x2 - x1);
    sbox[t]  = make_float4(x1, y1, x2, y2);
    sarea[t] = area;
    __syncthreads();

    unsigned long long mg = 0ull;
    const int j0 = max(q * 64, t + 1);
    const int j1 = q * 64 + 64;
    for (int j = j0; j < j1; ++j) {
        const float4 o = sbox[j];
        const float ih = fmaxf(fminf(y2, o.w) - fmaxf(y1, o.y), 0.0f);
        const float iw = fmaxf(fminf(x2, o.z) - fmaxf(x1, o.x), 0.0f);
        const float inter = ih * iw;
        const float uni   = area + sarea[j] - inter;
        // exact IEEE divide so the >0.4 decision matches JAX bit-for-bit
        const float iou = (uni > 0.0f) ? __fdiv_rn(inter, uni) : 0.0f;
        if (iou > 0.4f) mg |= 1ull << (j & 63);
    }
    g_mask[(b * RR + t) * 4 + q] = mg;
}

// ---- Stage 2: forward-clear greedy resolve + clip + big-first ordering ----
__global__ __launch_bounds__(64)
void nms_resolve_kernel(const float* __restrict__ roi, float* __restrict__ out, int write_tail) {
    __shared__ unsigned long long sm[RR][4];
    __shared__ int sidx[NSEL];
    __shared__ int sarea_i[NSEL];

    const int b = blockIdx.x;
    const int t = threadIdx.x;

    const unsigned long long* gm = g_mask + (size_t)b * RR * 4;
    for (int idx = t; idx < RR * 4; idx += 64)
        ((unsigned long long*)sm)[idx] = gm[idx];
    __syncthreads();

    if (t == 0) {
        int n = 0;
        unsigned long long alive1 = ~0ull, alive2 = ~0ull, alive3 = ~0ull;
        // group 0
        {
            unsigned long long a = ~0ull;
            while (a && n < NSEL) {
                const int k = __ffsll((long long)a) - 1;
                sidx[n++] = k;
                a &= ~((1ull << k) | sm[k][0]);
                alive1 &= ~sm[k][1]; alive2 &= ~sm[k][2]; alive3 &= ~sm[k][3];
            }
        }
        // group 1
        if (n < NSEL) {
            unsigned long long a = alive1;
            while (a && n < NSEL) {
                const int k = __ffsll((long long)a) - 1;
                const int i = 64 + k;
                sidx[n++] = i;
                a &= ~((1ull << k) | sm[i][1]);
                alive2 &= ~sm[i][2]; alive3 &= ~sm[i][3];
            }
        }
        // group 2
        if (n < NSEL) {
            unsigned long long a = alive2;
            while (a && n < NSEL) {
                const int k = __ffsll((long long)a) - 1;
                const int i = 128 + k;
                sidx[n++] = i;
                a &= ~((1ull << k) | sm[i][2]);
                alive3 &= ~sm[i][3];
            }
        }
        // group 3
        if (n < NSEL) {
            unsigned long long a = alive3;
            while (a && n < NSEL) {
                const int k = __ffsll((long long)a) - 1;
                const int i = 192 + k;
                sidx[n++] = i;
                a &= ~((1ull << k) | sm[i][3]);
            }
        }
        for (int q2 = n; q2 < NSEL; ++q2) sidx[q2] = RR - NSEL + q2;  // fill = 192 + q
    }
    __syncthreads();

    // Clip the 64 selected ROIs, publish for the pooling kernel, emit tail output.
    {
        const float4 rr = ((const float4*)roi)[b * RR + sidx[t]];
        int xmin = (int)fmaxf(0.0f, rr.x);
        int ymin = (int)fmaxf(0.0f, rr.y);
        int xmax = (int)fminf((float)WW, rr.x + rr.z);
        int ymax = (int)fminf((float)HH, rr.y + rr.w);
        fix_axis(xmin, xmax, PHW, WW);
        fix_axis(ymin, ymax, PHW, HH);
        int4 rc;
        rc.x = xmin; rc.y = ymin; rc.z = xmax - xmin; rc.w = ymax - ymin;
        g_roiclip[b * NSEL + t] = rc;
        sarea_i[t] = rc.z * rc.w;
        if (write_tail) {
            float* tp = out + (size_t)POOLED_ELEMS + (size_t)(b * NSEL + t) * 4;
            tp[0] = (float)rc.x; tp[1] = (float)rc.y;
            tp[2] = (float)rc.z; tp[3] = (float)rc.w;
        }
    }
    __syncthreads();

    // Rank ROIs by area descending (big-first schedule for the pool kernel).
    {
        const int a = sarea_i[t];
        int rank = 0;
#pragma unroll 8
        for (int j = 0; j < NSEL; ++j) {
            const int aj = sarea_i[j];
            rank += (aj > a) || (aj == a && j < t);
        }
        g_order[rank * BB + b] = b * NSEL + t;   // rank-major: big ROIs of all batches first
    }
}

__device__ __forceinline__ float4 f4max(float4 a, float4 b) {
    return make_float4(fmaxf(a.x, b.x), fmaxf(a.y, b.y),
                       fmaxf(a.z, b.z), fmaxf(a.w, b.w));
}

// ---- Stage 3: pooling. grid = 2048 (ROI x channel-half), 4 groups x 64 float4-lanes ----
__global__ __launch_bounds__(256)
void pool_kernel(const float* __restrict__ feat, float* __restrict__ out) {
    const int slot = g_order[blockIdx.x >> 1];
    const int half = blockIdx.x & 1;
    const int b  = slot >> 6;
    const int4 rc = g_roiclip[slot];
    const int x = rc.x, y = rc.y, w = rc.z, h = rc.w;
    const int lane = threadIdx.x & 63;
    const int g    = threadIdx.x >> 6;           // group 0..3
    const int t    = half * 64 + lane;           // float4 lane in [0,128)
    const int CV   = CC / 4;                     // 128 float4 per position

    const float4* __restrict__ fm = (const float4*)feat + (size_t)b * HH * WW * CV;
    float4* __restrict__ o = (float4*)out + (size_t)slot * (PHW * PHW) * CV;

    const float NEGF = -__int_as_float(0x7f800000);
    const float4 NEG4 = make_float4(NEGF, NEGF, NEGF, NEGF);

    // ---- 6x6 direct copy: 36 positions, 9 per group ----
#pragma unroll
    for (int k = 0; k < 9; ++k) {
        const int p = g * 9 + k;
        const int i = p / 6, j = p - 6 * i;
        o[(i * 7 + j) * CV + t] = fm[((y + i) * WW + (x + j)) * CV + t];
    }

    // ---- strips: groups 0,1 -> col strip rows 3g..3g+2; groups 2,3 -> row strip cols ----
#pragma unroll
    for (int k = 0; k < 3; ++k) {
        if (g < 2) {
            const int i = 3 * g + k;
            float4 a0 = NEG4, a1 = NEG4, a2 = NEG4, a3 = NEG4;
            const float4* row = fm + (size_t)(y + i) * WW * CV;
            int jj = x + 6;
            for (; jj + 3 < x + w; jj += 4) {
                a0 = f4max(a0, row[(jj    ) * CV + t]);
                a1 = f4max(a1, row[(jj + 1) * CV + t]);
                a2 = f4max(a2, row[(jj + 2) * CV + t]);
                a3 = f4max(a3, row[(jj + 3) * CV + t]);
            }
            for (; jj < x + w; ++jj) a0 = f4max(a0, row[jj * CV + t]);
            o[(i * 7 + 6) * CV + t] = f4max(f4max(a0, a1), f4max(a2, a3));
        } else {
            const int j = 3 * (g - 2) + k;
            float4 a0 = NEG4, a1 = NEG4, a2 = NEG4, a3 = NEG4;
            const float4* col = fm + (size_t)(x + j) * CV;
            int ii = y + 6;
            for (; ii + 3 < y + h; ii += 4) {
                a0 = f4max(a0, col[(ii    ) * WW * CV + t]);
                a1 = f4max(a1, col[(ii + 1) * WW * CV + t]);
                a2 = f4max(a2, col[(ii + 2) * WW * CV + t]);
                a3 = f4max(a3, col[(ii + 3) * WW * CV + t]);
            }
            for (; ii < y + h; ++ii) a0 = f4max(a0, col[ii * WW * CV + t]);
            o[(42 + j) * CV + t] = f4max(f4max(a0, a1), f4max(a2, a3));
        }
    }

    // ---- corner: rows interleaved x4 across groups, smem combine ----
    {
        __shared__ float4 sbuf[3][64];
        float4 a0 = NEG4, a1 = NEG4, a2 = NEG4, a3 = NEG4;
        for (int ii = y + 6 + g; ii < y + h; ii += 4) {
            const float4* row = fm + (size_t)ii * WW * CV;
            int jj = x + 6;
            for (; jj + 3 < x + w; jj += 4) {
                a0 = f4max(a0, row[(jj    ) * CV + t]);
                a1 = f4max(a1, row[(jj + 1) * CV + t]);
                a2 = f4max(a2, row[(jj + 2) * CV + t]);
                a3 = f4max(a3, row[(jj + 3) * CV + t]);
            }
            for (; jj < x + w; ++jj) a0 = f4max(a0, row[jj * CV + t]);
        }
        float4 a = f4max(f4max(a0, a1), f4max(a2, a3));
        if (g > 0) sbuf[g - 1][lane] = a;
        __syncthreads();
        if (g == 0) {
            a = f4max(a, f4max(sbuf[0][lane], f4max(sbuf[1][lane], sbuf[2][lane])));
            o[48 * CV + t] = a;
        }
    }
}

extern "C" void kernel_launch(void* const* d_in, const int* in_sizes, int n_in,
                              void* d_out, int out_size) {
    const float* feat = (const float*)d_in[0];
    const float* roi  = (const float*)d_in[1];
    // defensive: identify inputs by size (features = 33,554,432; roi = 16,384)
    if (n_in >= 2 && in_sizes[0] == BB * RR * 4) {
        feat = (const float*)d_in[1];
        roi  = (const float*)d_in[0];
    }
    float* out = (float*)d_out;
    const int write_tail = (out_size >= POOLED_ELEMS + BB * NSEL * 4) ? 1 : 0;

    nms_mask_kernel<<<dim3(BB, 4), RR>>>(roi);
    nms_resolve_kernel<<<BB, 64>>>(roi, out, write_tail);
    pool_kernel<<<BB * NSEL * 2, 256>>>(feat, out);
}

// round 8
// speedup vs baseline: 2.3216x; 1.0166x over previous
#include <cuda_runtime.h>
#include <cstdint>

#define BB   16
#define HH   64
#define WW   64
#define CC   512
#define RR   256
#define NSEL 64
#define PHW  7
#define POOLED_ELEMS (BB * NSEL * PHW * PHW * CC)  // 25,690,112

__device__ int4 g_roiclip[BB * NSEL];
__device__ int  g_order[BB * NSEL];                    // rank-major (big-first) schedule
__device__ unsigned long long g_mask[BB * RR * 4];     // upper-triangle suppression masks

__device__ __forceinline__ void fix_axis(int& mn, int& mx, int ps, int fs) {
    int pad = ps - (mx - mn);
    if (pad > 0) {
        if (mn < (pad >> 1))                { mn = 0;       mx = ps; }
        else if (fs - mx < ((1 + pad) >> 1)){ mn = fs - ps; mx = fs; }
        else { mn -= (pad >> 1); mx += (1 + pad) >> 1; }
    }
}

// ---- Stage 1: suppression masks, upper triangle (j > t), 32-wide chunks, 128 CTAs ----
__global__ __launch_bounds__(RR)
void nms_mask_kernel(const float* __restrict__ roi) {
    __shared__ float4 sbox[RR];   // x1, y1, x2, y2
    __shared__ float  sarea[RR];

    const int b = blockIdx.x;
    const int q = blockIdx.y;     // 32-wide j chunk, 0..7
    const int t = threadIdx.x;

    const float4 rv = ((const float4*)roi)[b * RR + t];
    const float x1 = rv.x, y1 = rv.y;
    const float x2 = rv.x + rv.z, y2 = rv.y + rv.w;
    const float area = (y2 - y1) * (x2 - x1);
    sbox[t]  = make_float4(x1, y1, x2, y2);
    sarea[t] = area;
    __syncthreads();

    unsigned mg = 0u;
    const int j0 = max(q * 32, t + 1);
    const int j1 = q * 32 + 32;
#pragma unroll 2
    for (int j = j0; j < j1; ++j) {
        const float4 o = sbox[j];
        const float ih = fmaxf(fminf(y2, o.w) - fmaxf(y1, o.y), 0.0f);
        const float iw = fmaxf(fminf(x2, o.z) - fmaxf(x1, o.x), 0.0f);
        const float inter = ih * iw;
        const float uni   = area + sarea[j] - inter;
        // exact IEEE divide so the >0.4 decision matches JAX bit-for-bit
        const float iou = (uni > 0.0f) ? __fdiv_rn(inter, uni) : 0.0f;
        if (iou > 0.4f) mg |= 1u << (j & 31);
    }
    // u32 alias of the u64 mask array: word q covers bits [32q, 32q+32) (little-endian)
    ((unsigned*)g_mask)[(b * RR + t) * 8 + q] = mg;
}

// ---- Stage 2: forward-clear greedy resolve + clip + big-first ordering ----
__global__ __launch_bounds__(64)
void nms_resolve_kernel(const float* __restrict__ roi, float* __restrict__ out, int write_tail) {
    __shared__ unsigned long long sm[RR][4];
    __shared__ int sidx[NSEL];
    __shared__ int sarea_i[NSEL];

    const int b = blockIdx.x;
    const int t = threadIdx.x;

    const unsigned long long* gm = g_mask + (size_t)b * RR * 4;
    for (int idx = t; idx < RR * 4; idx += 64)
        ((unsigned long long*)sm)[idx] = gm[idx];
    __syncthreads();

    if (t == 0) {
        int n = 0;
        unsigned long long alive1 = ~0ull, alive2 = ~0ull, alive3 = ~0ull;
        // group 0
        {
            unsigned long long a = ~0ull;
            while (a && n < NSEL) {
                const int k = __ffsll((long long)a) - 1;
                sidx[n++] = k;
                a &= ~((1ull << k) | sm[k][0]);
                alive1 &= ~sm[k][1]; alive2 &= ~sm[k][2]; alive3 &= ~sm[k][3];
            }
        }
        // group 1
        if (n < NSEL) {
            unsigned long long a = alive1;
            while (a && n < NSEL) {
                const int k = __ffsll((long long)a) - 1;
                const int i = 64 + k;
                sidx[n++] = i;
                a &= ~((1ull << k) | sm[i][1]);
                alive2 &= ~sm[i][2]; alive3 &= ~sm[i][3];
            }
        }
        // group 2
        if (n < NSEL) {
            unsigned long long a = alive2;
            while (a && n < NSEL) {
                const int k = __ffsll((long long)a) - 1;
                const int i = 128 + k;
                sidx[n++] = i;
                a &= ~((1ull << k) | sm[i][2]);
                alive3 &= ~sm[i][3];
            }
        }
        // group 3
        if (n < NSEL) {
            unsigned long long a = alive3;
            while (a && n < NSEL) {
                const int k = __ffsll((long long)a) - 1;
                const int i = 192 + k;
                sidx[n++] = i;
                a &= ~((1ull << k) | sm[i][3]);
            }
        }
        for (int q2 = n; q2 < NSEL; ++q2) sidx[q2] = RR - NSEL + q2;  // fill = 192 + q
    }
    __syncthreads();

    // Clip the 64 selected ROIs, publish for the pooling kernel, emit tail output.
    {
        const float4 rr = ((const float4*)roi)[b * RR + sidx[t]];
        int xmin = (int)fmaxf(0.0f, rr.x);
        int ymin = (int)fmaxf(0.0f, rr.y);
        int xmax = (int)fminf((float)WW, rr.x + rr.z);
        int ymax = (int)fminf((float)HH, rr.y + rr.w);
        fix_axis(xmin, xmax, PHW, WW);
        fix_axis(ymin, ymax, PHW, HH);
        int4 rc;
        rc.x = xmin; rc.y = ymin; rc.z = xmax - xmin; rc.w = ymax - ymin;
        g_roiclip[b * NSEL + t] = rc;
        sarea_i[t] = rc.z * rc.w;
        if (write_tail) {
            float* tp = out + (size_t)POOLED_ELEMS + (size_t)(b * NSEL + t) * 4;
            tp[0] = (float)rc.x; tp[1] = (float)rc.y;
            tp[2] = (float)rc.z; tp[3] = (float)rc.w;
        }
    }
    __syncthreads();

    // Rank ROIs by area descending (big-first schedule for the pool kernel).
    {
        const int a = sarea_i[t];
        int rank = 0;
#pragma unroll 8
        for (int j = 0; j < NSEL; ++j) {
            const int aj = sarea_i[j];
            rank += (aj > a) || (aj == a && j < t);
        }
        g_order[rank * BB + b] = b * NSEL + t;   // rank-major: big ROIs of all batches first
    }
}

__device__ __forceinline__ float4 f4max(float4 a, float4 b) {
    return make_float4(fmaxf(a.x, b.x), fmaxf(a.y, b.y),
                       fmaxf(a.z, b.z), fmaxf(a.w, b.w));
}

// ---- Stage 3: pooling. grid = 4096 (ROI x channel-quarter), 8 groups x 32 float4-lanes ----
__global__ __launch_bounds__(256)
void pool_kernel(const float* __restrict__ feat, float* __restrict__ out) {
    const int slot = g_order[blockIdx.x >> 2];
    const int quarter = blockIdx.x & 3;
    const int b  = slot >> 6;
    const int4 rc = g_roiclip[slot];
    const int x = rc.x, y = rc.y, w = rc.z, h = rc.w;
    const int lane = threadIdx.x & 31;
    const int g    = threadIdx.x >> 5;           // group 0..7
    const int t    = quarter * 32 + lane;        // float4 lane in [0,128)
    const int CV   = CC / 4;                     // 128 float4 per position

    const float4* __restrict__ fm = (const float4*)feat + (size_t)b * HH * WW * CV;
    float4* __restrict__ o = (float4*)out + (size_t)slot * (PHW * PHW) * CV;

    const float NEGF = -__int_as_float(0x7f800000);
    const float4 NEG4 = make_float4(NEGF, NEGF, NEGF, NEGF);

    // ---- 6x6 direct copy: 36 positions; groups 0-7 take 4 each, groups 0-3 one extra ----
#pragma unroll
    for (int k = 0; k < 4; ++k) {
        const int p = g * 4 + k;
        const int i = p / 6, j = p - 6 * i;
        o[(i * 7 + j) * CV + t] = fm[((y + i) * WW + (x + j)) * CV + t];
    }
    if (g < 4) {
        const int p = 32 + g;
        const int i = p / 6, j = p - 6 * i;
        o[(i * 7 + j) * CV + t] = fm[((y + i) * WW + (x + j)) * CV + t];
    }

    // ---- strips: 12 tasks (0-5 col-strip rows, 6-11 row-strip cols) over 8 groups ----
#pragma unroll
    for (int rep = 0; rep < 2; ++rep) {
        const int s = rep == 0 ? g : (g < 4 ? 8 + g : 12);
        if (s < 6) {
            const int i = s;
            float4 a0 = NEG4, a1 = NEG4, a2 = NEG4, a3 = NEG4;
            const float4* row = fm + (size_t)(y + i) * WW * CV;
            int jj = x + 6;
            for (; jj + 3 < x + w; jj += 4) {
                a0 = f4max(a0, row[(jj    ) * CV + t]);
                a1 = f4max(a1, row[(jj + 1) * CV + t]);
                a2 = f4max(a2, row[(jj + 2) * CV + t]);
                a3 = f4max(a3, row[(jj + 3) * CV + t]);
            }
            for (; jj < x + w; ++jj) a0 = f4max(a0, row[jj * CV + t]);
            o[(i * 7 + 6) * CV + t] = f4max(f4max(a0, a1), f4max(a2, a3));
        } else if (s < 12) {
            const int j = s - 6;
            float4 a0 = NEG4, a1 = NEG4, a2 = NEG4, a3 = NEG4;
            const float4* col = fm + (size_t)(x + j) * CV;
            int ii = y + 6;
            for (; ii + 3 < y + h; ii += 4) {
                a0 = f4max(a0, col[(ii    ) * WW * CV + t]);
                a1 = f4max(a1, col[(ii + 1) * WW * CV + t]);
                a2 = f4max(a2, col[(ii + 2) * WW * CV + t]);
                a3 = f4max(a3, col[(ii + 3) * WW * CV + t]);
            }
            for (; ii < y + h; ++ii) a0 = f4max(a0, col[ii * WW * CV + t]);
            o[(42 + j) * CV + t] = f4max(f4max(a0, a1), f4max(a2, a3));
        }
    }

    // ---- corner: rows interleaved x8 across groups, smem combine ----
    {
        __shared__ float4 sbuf[7][32];
        float4 a0 = NEG4, a1 = NEG4, a2 = NEG4, a3 = NEG4;
        for (int ii = y + 6 + g; ii < y + h; ii += 8) {
            const float4* row = fm + (size_t)ii * WW * CV;
            int jj = x + 6;
            for (; jj + 3 < x + w; jj += 4) {
                a0 = f4max(a0, row[(jj    ) * CV + t]);
                a1 = f4max(a1, row[(jj + 1) * CV + t]);
                a2 = f4max(a2, row[(jj + 2) * CV + t]);
                a3 = f4max(a3, row[(jj + 3) * CV + t]);
            }
            for (; jj < x + w; ++jj) a0 = f4max(a0, row[jj * CV + t]);
        }
        float4 a = f4max(f4max(a0, a1), f4max(a2, a3));
        if (g > 0) sbuf[g - 1][lane] = a;
        __syncthreads();
        if (g == 0) {
            float4 m01 = f4max(sbuf[0][lane], sbuf[1][lane]);
            float4 m23 = f4max(sbuf[2][lane], sbuf[3][lane]);
            float4 m45 = f4max(sbuf[4][lane], sbuf[5][lane]);
            a = f4max(f4max(a, sbuf[6][lane]), f4max(f4max(m01, m23), m45));
            o[48 * CV + t] = a;
        }
    }
}

extern "C" void kernel_launch(void* const* d_in, const int* in_sizes, int n_in,
                              void* d_out, int out_size) {
    const float* feat = (const float*)d_in[0];
    const float* roi  = (const float*)d_in[1];
    // defensive: identify inputs by size (features = 33,554,432; roi = 16,384)
    if (n_in >= 2 && in_sizes[0] == BB * RR * 4) {
        feat = (const float*)d_in[1];
        roi  = (const float*)d_in[0];
    }
    float* out = (float*)d_out;
    const int write_tail = (out_size >= POOLED_ELEMS + BB * NSEL * 4) ? 1 : 0;

    nms_mask_kernel<<<dim3(BB, 8), RR>>>(roi);
    nms_resolve_kernel<<<BB, 64>>>(roi, out, write_tail);
    pool_kernel<<<BB * NSEL * 4, 256>>>(feat, out);
}

// round 9
// speedup vs baseline: 2.4975x; 1.0758x over previous
#include <cuda_runtime.h>
#include <cstdint>

#define BB   16
#define HH   64
#define WW   64
#define CC   512
#define RR   256
#define NSEL 64
#define PHW  7
#define POOLED_ELEMS (BB * NSEL * PHW * PHW * CC)  // 25,690,112

__device__ int4 g_roiclip[BB * NSEL];
__device__ int  g_order[BB * NSEL];   // batch-major, big-first within batch

__device__ __forceinline__ void fix_axis(int& mn, int& mx, int ps, int fs) {
    int pad = ps - (mx - mn);
    if (pad > 0) {
        if (mn < (pad >> 1))                { mn = 0;       mx = ps; }
        else if (fs - mx < ((1 + pad) >> 1)){ mn = fs - ps; mx = fs; }
        else { mn -= (pad >> 1); mx += (1 + pad) >> 1; }
    }
}

// ---- Stage 1 (fused): masks + greedy resolve + clip + ordering. 16 CTAs x 1024 thr ----
__global__ __launch_bounds__(1024)
void nms_all_kernel(const float* __restrict__ roi, float* __restrict__ out, int write_tail) {
    __shared__ float4 sbox[RR];                  // x1, y1, x2, y2
    __shared__ float  sarea[RR];
    __shared__ unsigned long long sm[RR][4];     // upper-triangle suppression masks
    __shared__ int sidx[NSEL];
    __shared__ int sarea_i[NSEL];

    const int b   = blockIdx.x;
    const int tid = threadIdx.x;
    const int t   = tid & 255;                   // candidate row
    const int q   = tid >> 8;                    // 64-wide word 0..3

    if (q == 0) {
        const float4 rv = ((const float4*)roi)[b * RR + t];
        sbox[t]  = make_float4(rv.x, rv.y, rv.x + rv.z, rv.y + rv.w);
        sarea[t] = rv.w * rv.z;                  // (y2-y1)*(x2-x1) = h*w
    }
    __syncthreads();

    // Each thread: one 64-bit mask word of row t, upper triangle only (j > t).
    {
        const float4 me = sbox[t];
        const float area = sarea[t];
        unsigned long long mg = 0ull;
        const int j0 = max(q * 64, t + 1);
        const int j1 = q * 64 + 64;
        for (int j = j0; j < j1; ++j) {
            const float4 o = sbox[j];
            const float ih = fmaxf(fminf(me.w, o.w) - fmaxf(me.y, o.y), 0.0f);
            const float iw = fmaxf(fminf(me.z, o.z) - fmaxf(me.x, o.x), 0.0f);
            const float inter = ih * iw;
            const float uni   = area + sarea[j] - inter;
            // exact IEEE divide so the >0.4 decision matches JAX bit-for-bit
            const float iou = (uni > 0.0f) ? __fdiv_rn(inter, uni) : 0.0f;
            if (iou > 0.4f) mg |= 1ull << (j & 63);
        }
        sm[t][q] = mg;
    }
    __syncthreads();

    // Forward-clear greedy resolve: visit only still-alive boxes via ffsll.
    if (tid == 0) {
        int n = 0;
        unsigned long long alive1 = ~0ull, alive2 = ~0ull, alive3 = ~0ull;
        {
            unsigned long long a = ~0ull;
            while (a && n < NSEL) {
                const int k = __ffsll((long long)a) - 1;
                sidx[n++] = k;
                a &= ~((1ull << k) | sm[k][0]);
                alive1 &= ~sm[k][1]; alive2 &= ~sm[k][2]; alive3 &= ~sm[k][3];
            }
        }
        if (n < NSEL) {
            unsigned long long a = alive1;
            while (a && n < NSEL) {
                const int k = __ffsll((long long)a) - 1;
                const int i = 64 + k;
                sidx[n++] = i;
                a &= ~((1ull << k) | sm[i][1]);
                alive2 &= ~sm[i][2]; alive3 &= ~sm[i][3];
            }
        }
        if (n < NSEL) {
            unsigned long long a = alive2;
            while (a && n < NSEL) {
                const int k = __ffsll((long long)a) - 1;
                const int i = 128 + k;
                sidx[n++] = i;
                a &= ~((1ull << k) | sm[i][2]);
                alive3 &= ~sm[i][3];
            }
        }
        if (n < NSEL) {
            unsigned long long a = alive3;
            while (a && n < NSEL) {
                const int k = __ffsll((long long)a) - 1;
                const int i = 192 + k;
                sidx[n++] = i;
                a &= ~((1ull << k) | sm[i][3]);
            }
        }
        for (int q2 = n; q2 < NSEL; ++q2) sidx[q2] = RR - NSEL + q2;  // fill = 192 + q
    }
    __syncthreads();

    // Clip the 64 selected ROIs, publish for the pooling kernel, emit tail output.
    if (tid < NSEL) {
        const float4 rr = ((const float4*)roi)[b * RR + sidx[tid]];
        int xmin = (int)fmaxf(0.0f, rr.x);
        int ymin = (int)fmaxf(0.0f, rr.y);
        int xmax = (int)fminf((float)WW, rr.x + rr.z);
        int ymax = (int)fminf((float)HH, rr.y + rr.w);
        fix_axis(xmin, xmax, PHW, WW);
        fix_axis(ymin, ymax, PHW, HH);
        int4 rc;
        rc.x = xmin; rc.y = ymin; rc.z = xmax - xmin; rc.w = ymax - ymin;
        g_roiclip[b * NSEL + tid] = rc;
        sarea_i[tid] = rc.z * rc.w;
        if (write_tail) {
            float* tp = out + (size_t)POOLED_ELEMS + (size_t)(b * NSEL + tid) * 4;
            tp[0] = (float)rc.x; tp[1] = (float)rc.y;
            tp[2] = (float)rc.z; tp[3] = (float)rc.w;
        }
    }
    __syncthreads();

    // Rank by area desc. Batch-major order: keeps concurrent CTAs within ~2 batches
    // so the feature working set stays L2-resident (the critical reuse lever).
    if (tid < NSEL) {
        const int a = sarea_i[tid];
        int rank = 0;
#pragma unroll 8
        for (int j = 0; j < NSEL; ++j) {
            const int aj = sarea_i[j];
            rank += (aj > a) || (aj == a && j < tid);
        }
        g_order[b * NSEL + rank] = b * NSEL + tid;
    }
}

__device__ __forceinline__ float4 f4max(float4 a, float4 b) {
    return make_float4(fmaxf(a.x, b.x), fmaxf(a.y, b.y),
                       fmaxf(a.z, b.z), fmaxf(a.w, b.w));
}

// ---- Stage 2: pooling. grid = 4096 (ROI x channel-quarter), 8 groups x 32 float4-lanes ----
__global__ __launch_bounds__(256)
void pool_kernel(const float* __restrict__ feat, float* __restrict__ out) {
    const int slot = g_order[blockIdx.x >> 2];
    const int quarter = blockIdx.x & 3;
    const int b  = slot >> 6;
    const int4 rc = g_roiclip[slot];
    const int x = rc.x, y = rc.y, w = rc.z, h = rc.w;
    const int lane = threadIdx.x & 31;
    const int g    = threadIdx.x >> 5;           // group 0..7
    const int t    = quarter * 32 + lane;        // float4 lane in [0,128)
    const int CV   = CC / 4;                     // 128 float4 per position

    const float4* __restrict__ fm = (const float4*)feat + (size_t)b * HH * WW * CV;
    float4* __restrict__ o = (float4*)out + (size_t)slot * (PHW * PHW) * CV;

    const float NEGF = -__int_as_float(0x7f800000);
    const float4 NEG4 = make_float4(NEGF, NEGF, NEGF, NEGF);

    // ---- 6x6 direct copy: 36 positions; groups 0-7 take 4 each, groups 0-3 one extra ----
#pragma unroll
    for (int k = 0; k < 4; ++k) {
        const int p = g * 4 + k;
        const int i = p / 6, j = p - 6 * i;
        o[(i * 7 + j) * CV + t] = fm[((y + i) * WW + (x + j)) * CV + t];
    }
    if (g < 4) {
        const int p = 32 + g;
        const int i = p / 6, j = p - 6 * i;
        o[(i * 7 + j) * CV + t] = fm[((y + i) * WW + (x + j)) * CV + t];
    }

    // ---- strips: 12 tasks (0-5 col-strip rows, 6-11 row-strip cols) over 8 groups ----
#pragma unroll
    for (int rep = 0; rep < 2; ++rep) {
        const int s = rep == 0 ? g : (g < 4 ? 8 + g : 12);
        if (s < 6) {
            const int i = s;
            float4 a0 = NEG4, a1 = NEG4, a2 = NEG4, a3 = NEG4;
            const float4* row = fm + (size_t)(y + i) * WW * CV;
            int jj = x + 6;
            for (; jj + 3 < x + w; jj += 4) {
                a0 = f4max(a0, row[(jj    ) * CV + t]);
                a1 = f4max(a1, row[(jj + 1) * CV + t]);
                a2 = f4max(a2, row[(jj + 2) * CV + t]);
                a3 = f4max(a3, row[(jj + 3) * CV + t]);
            }
            for (; jj < x + w; ++jj) a0 = f4max(a0, row[jj * CV + t]);
            o[(i * 7 + 6) * CV + t] = f4max(f4max(a0, a1), f4max(a2, a3));
        } else if (s < 12) {
            const int j = s - 6;
            float4 a0 = NEG4, a1 = NEG4, a2 = NEG4, a3 = NEG4;
            const float4* col = fm + (size_t)(x + j) * CV;
            int ii = y + 6;
            for (; ii + 3 < y + h; ii += 4) {
                a0 = f4max(a0, col[(ii    ) * WW * CV + t]);
                a1 = f4max(a1, col[(ii + 1) * WW * CV + t]);
                a2 = f4max(a2, col[(ii + 2) * WW * CV + t]);
                a3 = f4max(a3, col[(ii + 3) * WW * CV + t]);
            }
            for (; ii < y + h; ++ii) a0 = f4max(a0, col[ii * WW * CV + t]);
            o[(42 + j) * CV + t] = f4max(f4max(a0, a1), f4max(a2, a3));
        }
    }

    // ---- corner: rows interleaved x8 across groups, smem combine ----
    {
        __shared__ float4 sbuf[7][32];
        float4 a0 = NEG4, a1 = NEG4, a2 = NEG4, a3 = NEG4;
        for (int ii = y + 6 + g; ii < y + h; ii += 8) {
            const float4* row = fm + (size_t)ii * WW * CV;
            int jj = x + 6;
            for (; jj + 3 < x + w; jj += 4) {
                a0 = f4max(a0, row[(jj    ) * CV + t]);
                a1 = f4max(a1, row[(jj + 1) * CV + t]);
                a2 = f4max(a2, row[(jj + 2) * CV + t]);
                a3 = f4max(a3, row[(jj + 3) * CV + t]);
            }
            for (; jj < x + w; ++jj) a0 = f4max(a0, row[jj * CV + t]);
        }
        float4 a = f4max(f4max(a0, a1), f4max(a2, a3));
        if (g > 0) sbuf[g - 1][lane] = a;
        __syncthreads();
        if (g == 0) {
            float4 m01 = f4max(sbuf[0][lane], sbuf[1][lane]);
            float4 m23 = f4max(sbuf[2][lane], sbuf[3][lane]);
            float4 m45 = f4max(sbuf[4][lane], sbuf[5][lane]);
            a = f4max(f4max(a, sbuf[6][lane]), f4max(f4max(m01, m23), m45));
            o[48 * CV + t] = a;
        }
    }
}

extern "C" void kernel_launch(void* const* d_in, const int* in_sizes, int n_in,
                              void* d_out, int out_size) {
    const float* feat = (const float*)d_in[0];
    const float* roi  = (const float*)d_in[1];
    // defensive: identify inputs by size (features = 33,554,432; roi = 16,384)
    if (n_in >= 2 && in_sizes[0] == BB * RR * 4) {
        feat = (const float*)d_in[1];
        roi  = (const float*)d_in[0];
    }
    float* out = (float*)d_out;
    const int write_tail = (out_size >= POOLED_ELEMS + BB * NSEL * 4) ? 1 : 0;

    nms_all_kernel<<<BB, 1024>>>(roi, out, write_tail);
    pool_kernel<<<BB * NSEL * 4, 256>>>(feat, out);
}